// round 1
// baseline (speedup 1.0000x reference)
#include <cuda_runtime.h>

// Reference analysis: _encode_batch sets every state to basis vector e_0
// regardless of input x. overlap[i,j] = conj(1)*1 = 1, |overlap|^2 = 1.
// Output = 2048x2048 float32 of all-ones. Pure STG bandwidth problem.

__global__ void fill_ones_f4(float4* __restrict__ out) {
    unsigned idx = blockIdx.x * blockDim.x + threadIdx.x;
    out[idx] = make_float4(1.0f, 1.0f, 1.0f, 1.0f);
}

__global__ void fill_ones_tail(float* __restrict__ out, int start, int n) {
    int i = start + blockIdx.x * blockDim.x + threadIdx.x;
    if (i < n) out[i] = 1.0f;
}

extern "C" void kernel_launch(void* const* d_in, const int* in_sizes, int n_in,
                              void* d_out, int out_size) {
    (void)d_in; (void)in_sizes; (void)n_in;
    float* out = (float*)d_out;

    int n4 = out_size >> 2;           // float4 count (out_size = 4194304 -> 1048576)
    if (n4 > 0) {
        const int threads = 256;
        int blocks = n4 / threads;    // exact for 1048576
        if (blocks * threads == n4) {
            fill_ones_f4<<<blocks, threads>>>((float4*)out);
        } else {
            // generic path: tail handled separately
            fill_ones_f4<<<blocks, threads>>>((float4*)out);
            int done = blocks * threads * 4;
            int rem = out_size - done;
            if (rem > 0)
                fill_ones_tail<<<(rem + 255) / 256, 256>>>(out, done, out_size);
            return;
        }
    }
    int done4 = (n4 / 256) * 256 * 4;
    // handle any scalar remainder (none for 4194304, but be safe)
    if (done4 < out_size && (out_size & 3)) {
        int start = out_size & ~3;
        fill_ones_tail<<<1, 4>>>(out, start, out_size);
    }
}

// round 3
// speedup vs baseline: 1.0386x; 1.0386x over previous
#include <cuda_runtime.h>

// Output = 2048x2048 float32 of all-ones (reference encodes every sample to
// basis state e_0 regardless of input; |<e0|e0>|^2 = 1 for all pairs).
//
// One-wave grid: 1024 blocks x 256 thr = 262144 threads; 1048576 float4
// stores -> exactly 4 independent STG.128 per thread (front-batched, no
// loop-carried deps). Output (16 MiB) stays resident in L2 (126 MB), so the
// bound is the LTS chip throughput (~6300 B/cyc), not HBM.

__global__ void __launch_bounds__(256) fill_ones_f4x4(float4* __restrict__ out) {
    const unsigned stride = 1024u * 256u;               // total threads
    unsigned idx = blockIdx.x * 256u + threadIdx.x;
    const float4 v = make_float4(1.0f, 1.0f, 1.0f, 1.0f);
    out[idx]              = v;
    out[idx + stride]     = v;
    out[idx + 2 * stride] = v;
    out[idx + 3 * stride] = v;
}

__global__ void fill_ones_generic(float* __restrict__ out, int n) {
    int i = blockIdx.x * blockDim.x + threadIdx.x;
    if (i < n) out[i] = 1.0f;
}

extern "C" void kernel_launch(void* const* d_in, const int* in_sizes, int n_in,
                              void* d_out, int out_size) {
    (void)d_in; (void)in_sizes; (void)n_in;
    float* out = (float*)d_out;

    const long long expected = 1024LL * 256 * 4 * 4;    // 4194304 floats
    if (out_size == expected) {
        fill_ones_f4x4<<<1024, 256>>>((float4*)out);
    } else {
        int blocks = (out_size + 255) / 256;
        fill_ones_generic<<<blocks, 256>>>(out, out_size);
    }
}